// round 16
// baseline (speedup 1.0000x reference)
#include <cuda_runtime.h>
#include <cuda_fp16.h>

#define HH 56
#define WW 56
#define CC 64
#define BB 4
#define HWP 3136           // 56*56
#define NPIX (BB*HWP)      // 12544
#define NDB  (NPIX/32)     // deform blocks = 392 (98 per batch, 8x4 px tiles)

// ---------------- packed f32x2 helpers ----------------
__device__ __forceinline__ unsigned long long fma2(unsigned long long a, unsigned long long b, unsigned long long c) {
    unsigned long long d;
    asm("fma.rn.f32x2 %0, %1, %2, %3;" : "=l"(d) : "l"(a), "l"(b), "l"(c));
    return d;
}
__device__ __forceinline__ __half2 u2h(unsigned int v) { return *reinterpret_cast<__half2*>(&v); }
__device__ __forceinline__ unsigned int h2u(__half2 h) { return *reinterpret_cast<unsigned int*>(&h); }
// half2 -> packed f32x2 in 64-bit reg
__device__ __forceinline__ unsigned long long h2f2(__half2 hh) {
    float2 f = __half22float2(hh);
    unsigned long long d;
    asm("mov.b64 %0, {%1, %2};" : "=l"(d) : "f"(f.x), "f"(f.y));
    return d;
}

// ---------------- scratch (device globals; no allocations) ----------------
__device__ __align__(16) __half g_xh [NPIX*CC];      // x in NHWC fp16 (conv + deform1 src)
__device__ __align__(16) __half g_o1h[NPIX*CC];      // out1 NHWC fp16 (deform2 src + combine)
__device__ __align__(16) __half g_o2h[NPIX*CC];      // out2 NHWC fp16 (combine)
__device__ __align__(16) float g_off3[NPIX*98];      // offset3 [pix][98]
__device__ __align__(16) float g_off2[NPIX*50];      // offset2 [pix][50]
__device__ __align__(16) float g_w7t [49*CC];        // w7 transposed [k][c]
__device__ __align__(16) float g_w5t [25*CC];        // w5 transposed [k][c]
__device__ __align__(16) float2 g_wp3[288*49];       // conv3 weight pairs [(ic*9+j)][o]
__device__ __align__(16) float2 g_wp2[288*25];       // conv2 weight pairs
__device__ __align__(16) float2 g_bp3[49];
__device__ __align__(16) float2 g_bp2[25];
__device__ __align__(16) float g_bs1[NDB*CC];        // per-block GAP partials (out1)
__device__ __align__(16) float g_bs2[NDB*CC];        // per-block GAP partials (out2)

// ---------------- prep: NCHW->NHWC fp16 transpose AND weight prep ---------
// blocks [0, 392): transpose; blocks [392, 456): weight tables.
__global__ void k_prep(const float* __restrict__ x,
                       const float* __restrict__ w7, const float* __restrict__ w5,
                       const float* __restrict__ w_off3, const float* __restrict__ b_off3,
                       const float* __restrict__ w_off2, const float* __restrict__ b_off2) {
    int bid = blockIdx.x;
    if (bid < BB*98) {
        __shared__ float tile[CC][33];
        int b  = bid / 98;
        int p0 = (bid % 98) * 32;
        int tid = threadIdx.x;
#pragma unroll
        for (int it = 0; it < 8; it++) {
            int idx = tid + it*256;
            int c = idx >> 5, pp = idx & 31;
            tile[c][pp] = x[((size_t)(b*CC + c))*HWP + p0 + pp];
        }
        __syncthreads();
        int c2 = tid & 63;
#pragma unroll
        for (int it = 0; it < 8; it++) {
            int pp2 = (tid >> 6) + it*4;
            float v = tile[c2][pp2];
            size_t idx = ((size_t)(b*HWP + p0 + pp2))*CC + c2;
            g_xh[idx] = __float2half(v);
        }
    } else {
        int tid = (bid - BB*98) * blockDim.x + threadIdx.x;
        int nthr = 64 * 256;
        for (int i = tid; i < CC*49; i += nthr) {
            int c = i / 49, k = i - c*49;
            g_w7t[k*CC + c] = w7[i];
        }
        for (int i = tid; i < CC*25; i += nthr) {
            int c = i / 25, k = i - c*25;
            g_w5t[k*CC + c] = w5[i];
        }
        for (int i = tid; i < 288*49; i += nthr) {
            int r = i / 49, o = i - r*49;
            int ic = r / 9, j = r - ic*9;
            g_wp3[i] = make_float2(w_off3[(o*32 + ic)*9 + j], w_off3[((o+49)*32 + ic)*9 + j]);
        }
        for (int i = tid; i < 288*25; i += nthr) {
            int r = i / 25, o = i - r*25;
            int ic = r / 9, j = r - ic*9;
            g_wp2[i] = make_float2(w_off2[(o*32 + ic)*9 + j], w_off2[((o+25)*32 + ic)*9 + j]);
        }
        if (tid < 49) g_bp3[tid] = make_float2(b_off3[tid], b_off3[tid+49]);
        if (tid >= 64 && tid < 89) g_bp2[tid-64] = make_float2(b_off2[tid-64], b_off2[tid-64+25]);
    }
}

// ---------------- fused grouped 3x3 convs, 14-pixel tiles, f32x2 ----------
// (R13 structure; stages from fp16 NHWC x, converts to fp32 in smem)
__global__ __launch_bounds__(96) void k_conv_fused(const __half* __restrict__ xh,
                                                   float* __restrict__ out3,
                                                   float* __restrict__ out2) {
    __shared__ float2 xsp[3][16][32];   // [dy][col][ic]: (x[ic], x[ic+32])
    int bid = blockIdx.x;
    int xt = bid & 3;
    int y  = (bid >> 2) % HH;
    int b  = bid / (4*HH);
    int x0 = xt * 14;
    int tid = threadIdx.x;

#pragma unroll
    for (int it = 0; it < 16; it++) {
        int i = tid + it*96;
        int ic  = i & 31;
        int col = (i >> 5) & 15;
        int dy  = i >> 9;
        int yy = y + dy - 1;
        int xx = x0 + col - 1;
        float v0 = 0.f, v1 = 0.f;
        if (yy >= 0 && yy < HH && xx >= 0 && xx < WW) {
            size_t base = ((size_t)((b*HH + yy)*WW + xx))*CC;
            v0 = __half2float(xh[base + ic]);
            v1 = __half2float(xh[base + 32 + ic]);
        }
        xsp[dy][col][ic] = make_float2(v0, v1);
    }
    __syncthreads();

    int t = tid;
    if (t < 74) {
        bool is3 = (t < 49);
        int o = is3 ? t : t - 49;
        int stride = is3 ? 49 : 25;
        const unsigned long long* wrow = is3 ? ((const unsigned long long*)g_wp3) + o
                                             : ((const unsigned long long*)g_wp2) + o;
        float2 bp = is3 ? g_bp3[o] : g_bp2[o];
        unsigned long long bdup;
        asm("mov.b64 %0, {%1, %2};" : "=l"(bdup) : "f"(bp.x), "f"(bp.y));

        unsigned long long acc[14];
#pragma unroll
        for (int p = 0; p < 14; p++) acc[p] = bdup;

#pragma unroll 2
        for (int ic = 0; ic < 32; ic++) {
            unsigned long long w2[9];
#pragma unroll
            for (int j = 0; j < 9; j++)
                w2[j] = wrow[(ic*9 + j)*stride];
#pragma unroll
            for (int dy = 0; dy < 3; dy++) {
                unsigned long long xm[16];
#pragma unroll
                for (int col = 0; col < 16; col++)
                    xm[col] = *(const unsigned long long*)&xsp[dy][col][ic];
#pragma unroll
                for (int dx = 0; dx < 3; dx++) {
                    unsigned long long wv = w2[dy*3 + dx];
#pragma unroll
                    for (int p = 0; p < 14; p++)
                        acc[p] = fma2(wv, xm[p+dx], acc[p]);
                }
            }
        }

        size_t pix = (size_t)(b*HH + y)*WW + x0;
        union { unsigned long long u; float f[2]; } cv;
        if (is3) {
#pragma unroll
            for (int p = 0; p < 14; p++) {
                cv.u = acc[p];
                out3[(pix + p)*98 + o]      = cv.f[0];
                out3[(pix + p)*98 + o + 49] = cv.f[1];
            }
        } else {
#pragma unroll
            for (int p = 0; p < 14; p++) {
                cv.u = acc[p];
                out2[(pix + p)*50 + o]      = cv.f[0];
                out2[(pix + p)*50 + o + 25] = cv.f[1];
            }
        }
    }
}

// ---------------- deformable depthwise conv: 8x4 px tile per block --------
// R13 structure; output is fp16-only (NHWC), GAP partials from fp32 accs.
template<int K, int PAD, int DIL>
__global__ __launch_bounds__(512) void k_deform(
                         const __half* __restrict__ src,  // NHWC fp16
                         const float* __restrict__ off,   // [pix][2*K*K]
                         const float* __restrict__ wt,    // [K*K][C] fp32
                         const float* __restrict__ bias,
                         __half* __restrict__ outh,       // NHWC fp16
                         float* __restrict__ bsum) {      // [NDB][CC] partials
    constexpr int K2 = K*K;
    constexpr int OFFC = 2*K2;
    __shared__ uint4  stap[32][K2];
    __shared__ float4 sred[16][16];

    int tile = blockIdx.x;
    int b  = tile / 98;
    int tt = tile - b*98;
    int ty = tt / 7, tx = tt - ty*7;
    int y0 = ty*4, x0 = tx*8;

    // phase 1: per-pixel per-tap corner coefficients + address precompute
    for (int i = threadIdx.x; i < 32*K2; i += 512) {
        int px = i / K2;
        int k  = i - px*K2;
        int y = y0 + (px >> 3);
        int x = x0 + (px & 7);
        int gp = (b*HH + y)*WW + x;
        float2 o2 = *(const float2*)(off + (size_t)gp*OFFC + 2*k);
        int ky = k / K, kx = k - ky*K;
        float py = (float)(y - PAD + DIL*ky) + o2.x;
        float px_ = (float)(x - PAD + DIL*kx) + o2.y;
        float fy = floorf(py), fx = floorf(px_);
        float ly = py - fy,  lx = px_ - fx;
        float hy = 1.f - ly, hx = 1.f - lx;
        int iy0 = (int)fy, ix0 = (int)fx;
        int iy1 = iy0 + 1, ix1 = ix0 + 1;
        float hxm = ((unsigned)ix0 < WW) ? hx : 0.f;
        float lxm = ((unsigned)ix1 < WW) ? lx : 0.f;
        float hym = ((unsigned)iy0 < HH) ? hy : 0.f;
        float lym = ((unsigned)iy1 < HH) ? ly : 0.f;
        float c00 = hym*hxm, c01 = hym*lxm, c10 = lym*hxm, c11 = lym*lxm;
        int jy0 = min(max(iy0,0), HH-1), jy1 = min(max(iy1,0), HH-1);
        int jx0 = min(max(ix0,0), WW-1), jx1 = min(max(ix1,0), WW-1);
        int a00 = (jy0*WW + jx0)*CC;
        int dxo = (jx1 - jx0)*CC;            // 0 or 64
        int dyo = (jy1 - jy0)*WW*CC;         // 0 or 3584 (fits 16 bits)
        stap[px][k] = make_uint4(h2u(__floats2half2_rn(c00, c01)),
                                 h2u(__floats2half2_rn(c10, c11)),
                                 (unsigned)a00,
                                 ((unsigned)dyo << 16) | (unsigned)dxo);
    }
    __syncthreads();

    int wid  = threadIdx.x >> 5;
    int lane = threadIdx.x & 31;
    int half_ = lane >> 4;
    int q = lane & 15;
    int p2 = (wid << 1) + half_;           // pixel within tile
    int y = y0 + (p2 >> 3);
    int x = x0 + (p2 & 7);
    int gp = (b*HH + y)*WW + x;
    int c4 = q*4;
    const __half* sb = src + (size_t)b*HWP*CC + c4;
    const float*  wp = wt + c4;

    ulonglong2 acc = *(const ulonglong2*)(bias + c4);

#pragma unroll
    for (int k = 0; k < K2; k++) {
        uint4 tp = *((const uint4*)&stap[p2][k]);   // one LDS.128
        int a00 = (int)tp.z;
        int dxo = (int)(tp.w & 0xffffu);
        int dyo = (int)(tp.w >> 16);
        const __half* r0 = sb + a00;
        uint2 q00 = *(const uint2*)(r0);
        uint2 q01 = *(const uint2*)(r0 + dxo);
        uint2 q10 = *(const uint2*)(r0 + dyo);
        uint2 q11 = *(const uint2*)(r0 + dyo + dxo);
        ulonglong2 wv = *(const ulonglong2*)(wp + k*CC);
        __half2 cA = u2h(tp.x), cB = u2h(tp.y);
        __half2 C00 = __half2half2(__low2half(cA));
        __half2 C01 = __half2half2(__high2half(cA));
        __half2 C10 = __half2half2(__low2half(cB));
        __half2 C11 = __half2half2(__high2half(cB));
        {   // ch 0-1: 1 HMUL2 + 3 HFMA2
            __half2 val = __hmul2(C00, u2h(q00.x));
            val = __hfma2(C01, u2h(q01.x), val);
            val = __hfma2(C10, u2h(q10.x), val);
            val = __hfma2(C11, u2h(q11.x), val);
            acc.x = fma2(wv.x, h2f2(val), acc.x);
        }
        {   // ch 2-3
            __half2 val = __hmul2(C00, u2h(q00.y));
            val = __hfma2(C01, u2h(q01.y), val);
            val = __hfma2(C10, u2h(q10.y), val);
            val = __hfma2(C11, u2h(q11.y), val);
            acc.y = fma2(wv.y, h2f2(val), acc.y);
        }
    }

    union { unsigned long long u; float f[2]; } a0, a1;
    a0.u = acc.x; a1.u = acc.y;
    {   // fp16-only output store (NHWC)
        uint2 st;
        st.x = h2u(__floats2half2_rn(a0.f[0], a0.f[1]));
        st.y = h2u(__floats2half2_rn(a1.f[0], a1.f[1]));
        *(uint2*)(outh + (size_t)gp*CC + c4) = st;
    }

    // ---- fused GAP partial (from fp32 accumulators): per-block sums ----
    float4 v = make_float4(a0.f[0], a0.f[1], a1.f[0], a1.f[1]);
    v.x += __shfl_xor_sync(0xffffffffu, v.x, 16);
    v.y += __shfl_xor_sync(0xffffffffu, v.y, 16);
    v.z += __shfl_xor_sync(0xffffffffu, v.z, 16);
    v.w += __shfl_xor_sync(0xffffffffu, v.w, 16);
    if (half_ == 0) sred[wid][q] = v;
    __syncthreads();
    if (threadIdx.x < 64) {
        int c = threadIdx.x;
        int qq = c >> 2, e = c & 3;
        float s = 0.f;
#pragma unroll
        for (int w = 0; w < 16; w++) {
            const float* f4 = (const float*)&sred[w][qq];
            s += f4[e];
        }
        bsum[(size_t)blockIdx.x*CC + c] = s;
    }
}

// ---------------- combine (computes attn per block) + NHWC -> NCHW --------
__global__ __launch_bounds__(256) void k_combine(float* __restrict__ out) {
    __shared__ float tile[CC][33];
    __shared__ float4 sh1[16][16], sh2[16][16];
    __shared__ float sattn[CC];
    int b  = blockIdx.x / 98;
    int p0 = (blockIdx.x % 98) * 32;
    int tid = threadIdx.x;

    // phase A: reduce the 98 per-block GAP partials for batch b -> attn
    {
        int q = tid & 15;
        int s = tid >> 4;
        float4 a1 = make_float4(0,0,0,0), a2 = make_float4(0,0,0,0);
        for (int j = s; j < 98; j += 16) {
            size_t idx = (size_t)(b*98 + j)*CC + q*4;
            float4 v1 = *(const float4*)(g_bs1 + idx);
            float4 v2 = *(const float4*)(g_bs2 + idx);
            a1.x += v1.x; a1.y += v1.y; a1.z += v1.z; a1.w += v1.w;
            a2.x += v2.x; a2.y += v2.y; a2.z += v2.z; a2.w += v2.w;
        }
        sh1[s][q] = a1; sh2[s][q] = a2;
        __syncthreads();
        if (s == 0) {
#pragma unroll
            for (int j = 1; j < 16; j++) {
                float4 v1 = sh1[j][q], v2 = sh2[j][q];
                a1.x += v1.x; a1.y += v1.y; a1.z += v1.z; a1.w += v1.w;
                a2.x += v2.x; a2.y += v2.y; a2.z += v2.z; a2.w += v2.w;
            }
            float s1[4] = {a1.x, a1.y, a1.z, a1.w};
            float s2[4] = {a2.x, a2.y, a2.z, a2.w};
#pragma unroll
            for (int i = 0; i < 4; i++) {
                float g1 = s1[i] * (1.f/3136.f), g2 = s2[i] * (1.f/3136.f);
                float m = fmaxf(g1, g2);
                float e1 = expf(g1 - m), e2 = expf(g2 - m);
                sattn[q*4 + i] = e1 / (e1 + e2);
            }
        }
        __syncthreads();
    }

    // phase B: weighted combine (fp16 sources) + transpose to NCHW
    int c = tid & 63;
    float a = sattn[c];
#pragma unroll
    for (int it = 0; it < 8; it++) {
        int pp = (tid >> 6) + it*4;
        size_t idx = ((size_t)(b*HWP + p0 + pp))*CC + c;
        float v1 = __half2float(g_o1h[idx]);
        float v2 = __half2float(g_o2h[idx]);
        tile[c][pp] = v1*a + v2*(1.f - a);
    }
    __syncthreads();
#pragma unroll
    for (int it = 0; it < 8; it++) {
        int idx = tid + it*256;
        int cc = idx >> 5, pp = idx & 31;
        out[((size_t)(b*CC + cc))*HWP + p0 + pp] = tile[cc][pp];
    }
}

// ---------------- launcher ----------------
extern "C" void kernel_launch(void* const* d_in, const int* in_sizes, int n_in,
                              void* d_out, int out_size) {
    const float* x      = (const float*)d_in[0];
    const float* w_off3 = (const float*)d_in[1];
    const float* b_off3 = (const float*)d_in[2];
    const float* w_off2 = (const float*)d_in[3];
    const float* b_off2 = (const float*)d_in[4];
    const float* w7     = (const float*)d_in[5];
    const float* b7     = (const float*)d_in[6];
    const float* w5     = (const float*)d_in[7];
    const float* b5     = (const float*)d_in[8];
    float* out = (float*)d_out;

    float *p_off3, *p_off2, *p_w7t, *p_w5t, *p_bs1, *p_bs2;
    __half *p_xh, *p_o1h, *p_o2h;
    cudaGetSymbolAddress((void**)&p_xh,   g_xh);
    cudaGetSymbolAddress((void**)&p_o1h,  g_o1h);
    cudaGetSymbolAddress((void**)&p_o2h,  g_o2h);
    cudaGetSymbolAddress((void**)&p_off3, g_off3);
    cudaGetSymbolAddress((void**)&p_off2, g_off2);
    cudaGetSymbolAddress((void**)&p_w7t,  g_w7t);
    cudaGetSymbolAddress((void**)&p_w5t,  g_w5t);
    cudaGetSymbolAddress((void**)&p_bs1,  g_bs1);
    cudaGetSymbolAddress((void**)&p_bs2,  g_bs2);

    k_prep<<<BB*98 + 64, 256>>>(x, w7, w5, w_off3, b_off3, w_off2, b_off2);

    k_conv_fused<<<BB*HH*4, 96>>>(p_xh, p_off3, p_off2);

    k_deform<7,9,3><<<NDB, 512>>>(p_xh,  p_off3, p_w7t, b7, p_o1h, p_bs1);
    k_deform<5,6,3><<<NDB, 512>>>(p_o1h, p_off2, p_w5t, b5, p_o2h, p_bs2);

    k_combine<<<BB*98, 256>>>(out);
}

// round 17
// speedup vs baseline: 1.0011x; 1.0011x over previous
#include <cuda_runtime.h>
#include <cuda_fp16.h>

#define HH 56
#define WW 56
#define CC 64
#define BB 4
#define HWP 3136           // 56*56
#define NPIX (BB*HWP)      // 12544
#define NDB  (NPIX/32)     // deform blocks = 392 (98 per batch, 8x4 px tiles)

// ---------------- packed f32x2 helpers ----------------
__device__ __forceinline__ unsigned long long fma2(unsigned long long a, unsigned long long b, unsigned long long c) {
    unsigned long long d;
    asm("fma.rn.f32x2 %0, %1, %2, %3;" : "=l"(d) : "l"(a), "l"(b), "l"(c));
    return d;
}
__device__ __forceinline__ __half2 u2h(unsigned int v) { return *reinterpret_cast<__half2*>(&v); }
__device__ __forceinline__ unsigned int h2u(__half2 h) { return *reinterpret_cast<unsigned int*>(&h); }
// half2 -> packed f32x2 in 64-bit reg
__device__ __forceinline__ unsigned long long h2f2(__half2 hh) {
    float2 f = __half22float2(hh);
    unsigned long long d;
    asm("mov.b64 %0, {%1, %2};" : "=l"(d) : "f"(f.x), "f"(f.y));
    return d;
}

// ---------------- scratch (device globals; no allocations) ----------------
__device__ __align__(16) float g_xcl [NPIX*CC];      // x in NHWC fp32 (conv source)
__device__ __align__(16) __half g_xh [NPIX*CC];      // x in NHWC fp16 (deform1 gather src)
__device__ __align__(16) __half g_o1h[NPIX*CC];      // out1 NHWC fp16 (deform2 src + combine)
__device__ __align__(16) __half g_o2h[NPIX*CC];      // out2 NHWC fp16 (combine)
__device__ __align__(16) float g_off3[NPIX*98];      // offset3 [pix][98]
__device__ __align__(16) float g_off2[NPIX*50];      // offset2 [pix][50]
__device__ __align__(16) float g_w7t [49*CC];        // w7 transposed [k][c]
__device__ __align__(16) float g_w5t [25*CC];        // w5 transposed [k][c]
__device__ __align__(16) float2 g_wp3[288*49];       // conv3 weight pairs [(ic*9+j)][o]
__device__ __align__(16) float2 g_wp2[288*25];       // conv2 weight pairs
__device__ __align__(16) float2 g_bp3[49];
__device__ __align__(16) float2 g_bp2[25];
__device__ __align__(16) float g_bs1[NDB*CC];        // per-block GAP partials (out1)
__device__ __align__(16) float g_bs2[NDB*CC];        // per-block GAP partials (out2)

// ---------------- prep: NCHW->NHWC transpose (+fp16) AND weight prep ------
// blocks [0, 392): transpose; blocks [392, 456): weight tables.
__global__ void k_prep(const float* __restrict__ x,
                       const float* __restrict__ w7, const float* __restrict__ w5,
                       const float* __restrict__ w_off3, const float* __restrict__ b_off3,
                       const float* __restrict__ w_off2, const float* __restrict__ b_off2) {
    int bid = blockIdx.x;
    if (bid < BB*98) {
        __shared__ float tile[CC][33];
        int b  = bid / 98;
        int p0 = (bid % 98) * 32;
        int tid = threadIdx.x;
#pragma unroll
        for (int it = 0; it < 8; it++) {
            int idx = tid + it*256;
            int c = idx >> 5, pp = idx & 31;
            tile[c][pp] = x[((size_t)(b*CC + c))*HWP + p0 + pp];
        }
        __syncthreads();
        int c2 = tid & 63;
#pragma unroll
        for (int it = 0; it < 8; it++) {
            int pp2 = (tid >> 6) + it*4;
            float v = tile[c2][pp2];
            size_t idx = ((size_t)(b*HWP + p0 + pp2))*CC + c2;
            g_xcl[idx] = v;
            g_xh[idx]  = __float2half(v);
        }
    } else {
        int tid = (bid - BB*98) * blockDim.x + threadIdx.x;
        int nthr = 64 * 256;
        for (int i = tid; i < CC*49; i += nthr) {
            int c = i / 49, k = i - c*49;
            g_w7t[k*CC + c] = w7[i];
        }
        for (int i = tid; i < CC*25; i += nthr) {
            int c = i / 25, k = i - c*25;
            g_w5t[k*CC + c] = w5[i];
        }
        for (int i = tid; i < 288*49; i += nthr) {
            int r = i / 49, o = i - r*49;
            int ic = r / 9, j = r - ic*9;
            g_wp3[i] = make_float2(w_off3[(o*32 + ic)*9 + j], w_off3[((o+49)*32 + ic)*9 + j]);
        }
        for (int i = tid; i < 288*25; i += nthr) {
            int r = i / 25, o = i - r*25;
            int ic = r / 9, j = r - ic*9;
            g_wp2[i] = make_float2(w_off2[(o*32 + ic)*9 + j], w_off2[((o+25)*32 + ic)*9 + j]);
        }
        if (tid < 49) g_bp3[tid] = make_float2(b_off3[tid], b_off3[tid+49]);
        if (tid >= 64 && tid < 89) g_bp2[tid-64] = make_float2(b_off2[tid-64], b_off2[tid-64+25]);
    }
}

// ---------------- fused grouped 3x3 convs, 14-pixel tiles, f32x2 ----------
// (exact R13/R15 structure — best known; fp32 x source for error margin)
__global__ __launch_bounds__(96) void k_conv_fused(const float* __restrict__ xcl,
                                                   float* __restrict__ out3,
                                                   float* __restrict__ out2) {
    __shared__ float2 xsp[3][16][32];   // [dy][col][ic]: (x[ic], x[ic+32])
    int bid = blockIdx.x;
    int xt = bid & 3;
    int y  = (bid >> 2) % HH;
    int b  = bid / (4*HH);
    int x0 = xt * 14;
    int tid = threadIdx.x;

#pragma unroll
    for (int it = 0; it < 16; it++) {
        int i = tid + it*96;
        int ic  = i & 31;
        int col = (i >> 5) & 15;
        int dy  = i >> 9;
        int yy = y + dy - 1;
        int xx = x0 + col - 1;
        float v0 = 0.f, v1 = 0.f;
        if (yy >= 0 && yy < HH && xx >= 0 && xx < WW) {
            size_t base = ((size_t)((b*HH + yy)*WW + xx))*CC;
            v0 = xcl[base + ic];
            v1 = xcl[base + 32 + ic];
        }
        xsp[dy][col][ic] = make_float2(v0, v1);
    }
    __syncthreads();

    int t = tid;
    if (t < 74) {
        bool is3 = (t < 49);
        int o = is3 ? t : t - 49;
        int stride = is3 ? 49 : 25;
        const unsigned long long* wrow = is3 ? ((const unsigned long long*)g_wp3) + o
                                             : ((const unsigned long long*)g_wp2) + o;
        float2 bp = is3 ? g_bp3[o] : g_bp2[o];
        unsigned long long bdup;
        asm("mov.b64 %0, {%1, %2};" : "=l"(bdup) : "f"(bp.x), "f"(bp.y));

        unsigned long long acc[14];
#pragma unroll
        for (int p = 0; p < 14; p++) acc[p] = bdup;

#pragma unroll 2
        for (int ic = 0; ic < 32; ic++) {
            unsigned long long w2[9];
#pragma unroll
            for (int j = 0; j < 9; j++)
                w2[j] = wrow[(ic*9 + j)*stride];
#pragma unroll
            for (int dy = 0; dy < 3; dy++) {
                unsigned long long xm[16];
#pragma unroll
                for (int col = 0; col < 16; col++)
                    xm[col] = *(const unsigned long long*)&xsp[dy][col][ic];
#pragma unroll
                for (int dx = 0; dx < 3; dx++) {
                    unsigned long long wv = w2[dy*3 + dx];
#pragma unroll
                    for (int p = 0; p < 14; p++)
                        acc[p] = fma2(wv, xm[p+dx], acc[p]);
                }
            }
        }

        size_t pix = (size_t)(b*HH + y)*WW + x0;
        union { unsigned long long u; float f[2]; } cv;
        if (is3) {
#pragma unroll
            for (int p = 0; p < 14; p++) {
                cv.u = acc[p];
                out3[(pix + p)*98 + o]      = cv.f[0];
                out3[(pix + p)*98 + o + 49] = cv.f[1];
            }
        } else {
#pragma unroll
            for (int p = 0; p < 14; p++) {
                cv.u = acc[p];
                out2[(pix + p)*50 + o]      = cv.f[0];
                out2[(pix + p)*50 + o + 25] = cv.f[1];
            }
        }
    }
}

// ---------------- deformable depthwise conv: 8x4 px tile per block --------
// R13 structure; output is fp16-only (NHWC), GAP partials from fp32 accs.
template<int K, int PAD, int DIL>
__global__ __launch_bounds__(512) void k_deform(
                         const __half* __restrict__ src,  // NHWC fp16
                         const float* __restrict__ off,   // [pix][2*K*K]
                         const float* __restrict__ wt,    // [K*K][C] fp32
                         const float* __restrict__ bias,
                         __half* __restrict__ outh,       // NHWC fp16
                         float* __restrict__ bsum) {      // [NDB][CC] partials
    constexpr int K2 = K*K;
    constexpr int OFFC = 2*K2;
    __shared__ uint4  stap[32][K2];
    __shared__ float4 sred[16][16];

    int tile = blockIdx.x;
    int b  = tile / 98;
    int tt = tile - b*98;
    int ty = tt / 7, tx = tt - ty*7;
    int y0 = ty*4, x0 = tx*8;

    // phase 1: per-pixel per-tap corner coefficients + address precompute
    for (int i = threadIdx.x; i < 32*K2; i += 512) {
        int px = i / K2;
        int k  = i - px*K2;
        int y = y0 + (px >> 3);
        int x = x0 + (px & 7);
        int gp = (b*HH + y)*WW + x;
        float2 o2 = *(const float2*)(off + (size_t)gp*OFFC + 2*k);
        int ky = k / K, kx = k - ky*K;
        float py = (float)(y - PAD + DIL*ky) + o2.x;
        float px_ = (float)(x - PAD + DIL*kx) + o2.y;
        float fy = floorf(py), fx = floorf(px_);
        float ly = py - fy,  lx = px_ - fx;
        float hy = 1.f - ly, hx = 1.f - lx;
        int iy0 = (int)fy, ix0 = (int)fx;
        int iy1 = iy0 + 1, ix1 = ix0 + 1;
        float hxm = ((unsigned)ix0 < WW) ? hx : 0.f;
        float lxm = ((unsigned)ix1 < WW) ? lx : 0.f;
        float hym = ((unsigned)iy0 < HH) ? hy : 0.f;
        float lym = ((unsigned)iy1 < HH) ? ly : 0.f;
        float c00 = hym*hxm, c01 = hym*lxm, c10 = lym*hxm, c11 = lym*lxm;
        int jy0 = min(max(iy0,0), HH-1), jy1 = min(max(iy1,0), HH-1);
        int jx0 = min(max(ix0,0), WW-1), jx1 = min(max(ix1,0), WW-1);
        int a00 = (jy0*WW + jx0)*CC;
        int dxo = (jx1 - jx0)*CC;            // 0 or 64
        int dyo = (jy1 - jy0)*WW*CC;         // 0 or 3584 (fits 16 bits)
        stap[px][k] = make_uint4(h2u(__floats2half2_rn(c00, c01)),
                                 h2u(__floats2half2_rn(c10, c11)),
                                 (unsigned)a00,
                                 ((unsigned)dyo << 16) | (unsigned)dxo);
    }
    __syncthreads();

    int wid  = threadIdx.x >> 5;
    int lane = threadIdx.x & 31;
    int half_ = lane >> 4;
    int q = lane & 15;
    int p2 = (wid << 1) + half_;           // pixel within tile
    int y = y0 + (p2 >> 3);
    int x = x0 + (p2 & 7);
    int gp = (b*HH + y)*WW + x;
    int c4 = q*4;
    const __half* sb = src + (size_t)b*HWP*CC + c4;
    const float*  wp = wt + c4;

    ulonglong2 acc = *(const ulonglong2*)(bias + c4);

#pragma unroll
    for (int k = 0; k < K2; k++) {
        uint4 tp = *((const uint4*)&stap[p2][k]);   // one LDS.128
        int a00 = (int)tp.z;
        int dxo = (int)(tp.w & 0xffffu);
        int dyo = (int)(tp.w >> 16);
        const __half* r0 = sb + a00;
        uint2 q00 = *(const uint2*)(r0);
        uint2 q01 = *(const uint2*)(r0 + dxo);
        uint2 q10 = *(const uint2*)(r0 + dyo);
        uint2 q11 = *(const uint2*)(r0 + dyo + dxo);
        ulonglong2 wv = *(const ulonglong2*)(wp + k*CC);
        __half2 cA = u2h(tp.x), cB = u2h(tp.y);
        __half2 C00 = __half2half2(__low2half(cA));
        __half2 C01 = __half2half2(__high2half(cA));
        __half2 C10 = __half2half2(__low2half(cB));
        __half2 C11 = __half2half2(__high2half(cB));
        {   // ch 0-1: 1 HMUL2 + 3 HFMA2
            __half2 val = __hmul2(C00, u2h(q00.x));
            val = __hfma2(C01, u2h(q01.x), val);
            val = __hfma2(C10, u2h(q10.x), val);
            val = __hfma2(C11, u2h(q11.x), val);
            acc.x = fma2(wv.x, h2f2(val), acc.x);
        }
        {   // ch 2-3
            __half2 val = __hmul2(C00, u2h(q00.y));
            val = __hfma2(C01, u2h(q01.y), val);
            val = __hfma2(C10, u2h(q10.y), val);
            val = __hfma2(C11, u2h(q11.y), val);
            acc.y = fma2(wv.y, h2f2(val), acc.y);
        }
    }

    union { unsigned long long u; float f[2]; } a0, a1;
    a0.u = acc.x; a1.u = acc.y;
    {   // fp16-only output store (NHWC)
        uint2 st;
        st.x = h2u(__floats2half2_rn(a0.f[0], a0.f[1]));
        st.y = h2u(__floats2half2_rn(a1.f[0], a1.f[1]));
        *(uint2*)(outh + (size_t)gp*CC + c4) = st;
    }

    // ---- fused GAP partial (from fp32 accumulators): per-block sums ----
    float4 v = make_float4(a0.f[0], a0.f[1], a1.f[0], a1.f[1]);
    v.x += __shfl_xor_sync(0xffffffffu, v.x, 16);
    v.y += __shfl_xor_sync(0xffffffffu, v.y, 16);
    v.z += __shfl_xor_sync(0xffffffffu, v.z, 16);
    v.w += __shfl_xor_sync(0xffffffffu, v.w, 16);
    if (half_ == 0) sred[wid][q] = v;
    __syncthreads();
    if (threadIdx.x < 64) {
        int c = threadIdx.x;
        int qq = c >> 2, e = c & 3;
        float s = 0.f;
#pragma unroll
        for (int w = 0; w < 16; w++) {
            const float* f4 = (const float*)&sred[w][qq];
            s += f4[e];
        }
        bsum[(size_t)blockIdx.x*CC + c] = s;
    }
}

// ---------------- combine (computes attn per block) + NHWC -> NCHW --------
__global__ __launch_bounds__(256) void k_combine(float* __restrict__ out) {
    __shared__ float tile[CC][33];
    __shared__ float4 sh1[16][16], sh2[16][16];
    __shared__ float sattn[CC];
    int b  = blockIdx.x / 98;
    int p0 = (blockIdx.x % 98) * 32;
    int tid = threadIdx.x;

    // phase A: reduce the 98 per-block GAP partials for batch b -> attn
    {
        int q = tid & 15;
        int s = tid >> 4;
        float4 a1 = make_float4(0,0,0,0), a2 = make_float4(0,0,0,0);
        for (int j = s; j < 98; j += 16) {
            size_t idx = (size_t)(b*98 + j)*CC + q*4;
            float4 v1 = *(const float4*)(g_bs1 + idx);
            float4 v2 = *(const float4*)(g_bs2 + idx);
            a1.x += v1.x; a1.y += v1.y; a1.z += v1.z; a1.w += v1.w;
            a2.x += v2.x; a2.y += v2.y; a2.z += v2.z; a2.w += v2.w;
        }
        sh1[s][q] = a1; sh2[s][q] = a2;
        __syncthreads();
        if (s == 0) {
#pragma unroll
            for (int j = 1; j < 16; j++) {
                float4 v1 = sh1[j][q], v2 = sh2[j][q];
                a1.x += v1.x; a1.y += v1.y; a1.z += v1.z; a1.w += v1.w;
                a2.x += v2.x; a2.y += v2.y; a2.z += v2.z; a2.w += v2.w;
            }
            float s1[4] = {a1.x, a1.y, a1.z, a1.w};
            float s2[4] = {a2.x, a2.y, a2.z, a2.w};
#pragma unroll
            for (int i = 0; i < 4; i++) {
                float g1 = s1[i] * (1.f/3136.f), g2 = s2[i] * (1.f/3136.f);
                float m = fmaxf(g1, g2);
                float e1 = expf(g1 - m), e2 = expf(g2 - m);
                sattn[q*4 + i] = e1 / (e1 + e2);
            }
        }
        __syncthreads();
    }

    // phase B: weighted combine (vectorized uint2 fp16 loads) + transpose
    {
        int q   = tid & 15;     // channel quad
        int prw = tid >> 4;     // pixel row slot (0..15)
        float4 a4 = *(const float4*)(sattn + q*4);
#pragma unroll
        for (int it = 0; it < 2; it++) {
            int pp = prw + it*16;
            size_t idx = ((size_t)(b*HWP + p0 + pp))*CC + q*4;
            uint2 v1 = *(const uint2*)(g_o1h + idx);
            uint2 v2 = *(const uint2*)(g_o2h + idx);
            float2 f1a = __half22float2(u2h(v1.x));
            float2 f1b = __half22float2(u2h(v1.y));
            float2 f2a = __half22float2(u2h(v2.x));
            float2 f2b = __half22float2(u2h(v2.y));
            tile[q*4+0][pp] = f1a.x*a4.x + f2a.x*(1.f - a4.x);
            tile[q*4+1][pp] = f1a.y*a4.y + f2a.y*(1.f - a4.y);
            tile[q*4+2][pp] = f1b.x*a4.z + f2b.x*(1.f - a4.z);
            tile[q*4+3][pp] = f1b.y*a4.w + f2b.y*(1.f - a4.w);
        }
    }
    __syncthreads();
#pragma unroll
    for (int it = 0; it < 8; it++) {
        int idx = tid + it*256;
        int cc = idx >> 5, pp = idx & 31;
        out[((size_t)(b*CC + cc))*HWP + p0 + pp] = tile[cc][pp];
    }
}

// ---------------- launcher ----------------
extern "C" void kernel_launch(void* const* d_in, const int* in_sizes, int n_in,
                              void* d_out, int out_size) {
    const float* x      = (const float*)d_in[0];
    const float* w_off3 = (const float*)d_in[1];
    const float* b_off3 = (const float*)d_in[2];
    const float* w_off2 = (const float*)d_in[3];
    const float* b_off2 = (const float*)d_in[4];
    const float* w7     = (const float*)d_in[5];
    const float* b7     = (const float*)d_in[6];
    const float* w5     = (const float*)d_in[7];
    const float* b5     = (const float*)d_in[8];
    float* out = (float*)d_out;

    float *p_xcl, *p_off3, *p_off2, *p_w7t, *p_w5t, *p_bs1, *p_bs2;
    __half *p_xh, *p_o1h, *p_o2h;
    cudaGetSymbolAddress((void**)&p_xcl,  g_xcl);
    cudaGetSymbolAddress((void**)&p_xh,   g_xh);
    cudaGetSymbolAddress((void**)&p_o1h,  g_o1h);
    cudaGetSymbolAddress((void**)&p_o2h,  g_o2h);
    cudaGetSymbolAddress((void**)&p_off3, g_off3);
    cudaGetSymbolAddress((void**)&p_off2, g_off2);
    cudaGetSymbolAddress((void**)&p_w7t,  g_w7t);
    cudaGetSymbolAddress((void**)&p_w5t,  g_w5t);
    cudaGetSymbolAddress((void**)&p_bs1,  g_bs1);
    cudaGetSymbolAddress((void**)&p_bs2,  g_bs2);

    k_prep<<<BB*98 + 64, 256>>>(x, w7, w5, w_off3, b_off3, w_off2, b_off2);

    k_conv_fused<<<BB*HH*4, 96>>>(p_xcl, p_off3, p_off2);

    k_deform<7,9,3><<<NDB, 512>>>(p_xh,  p_off3, p_w7t, b7, p_o1h, p_bs1);
    k_deform<5,6,3><<<NDB, 512>>>(p_o1h, p_off2, p_w5t, b5, p_o2h, p_bs2);

    k_combine<<<BB*98, 256>>>(out);
}